// round 3
// baseline (speedup 1.0000x reference)
#include <cuda_runtime.h>
#include <math.h>

// Problem: B=2, S=2048, D=1024, N_COMPRESS=64, RANK=64, TOP_K=2
#define TOKENS 4096
#define DIM    1024
#define NEXP   64
#define RANK   64
#define CAP    8192
#define NSPL_R 8          // router D-splits (128 d each)
#define DSPL_R 128
#define NSPLIT 4          // proj D-splits (256 d each)
#define DSPL   256
#define TILE_P 128        // picks per proj tile

#define OFF_IDX (TOKENS * RANK)
#define OFF_W   (TOKENS * RANK + TOKENS*2)

typedef unsigned long long ull;

__device__ __forceinline__ ull fma2(ull a, ull b, ull c) {
    ull d; asm("fma.rn.f32x2 %0, %1, %2, %3;" : "=l"(d) : "l"(a), "l"(b), "l"(c)); return d;
}
__device__ __forceinline__ float2 unpack2(ull v) {
    float2 r; asm("mov.b64 {%0, %1}, %2;" : "=f"(r.x), "=f"(r.y) : "l"(v)); return r;
}
__device__ __forceinline__ ull swap64(ull v) {
    ull r;
    asm("{ .reg .b32 lo, hi; mov.b64 {lo, hi}, %1; mov.b64 %0, {hi, lo}; }"
        : "=l"(r) : "l"(v));
    return r;
}

// ---- scratch (device globals) ----
__device__ int   g_cnt[NEXP];
__device__ int   g_list[NEXP * CAP];
__device__ float g_w[TOKENS * 2];
__device__ float g_part[NSPL_R * TOKENS * NEXP];          // router partials
__device__ float g_scratch[NSPLIT * TOKENS * 2 * RANK];   // proj partials

// ============================================================
// Kernel 1: router partial scores. grid (32 token-blocks, 8 D-splits),
// 128 threads. Block tile: 128 tokens x 64 experts over 128 d.
// 8x8 per-thread tile, f32x2 packed over OUTPUT pairs (P/Q swap trick).
// SMEM is k-major so both operand pairs are contiguous.
// ============================================================
__global__ __launch_bounds__(128) void k_router(
    const float* __restrict__ x, const float* __restrict__ W)
{
    __shared__ __align__(16) float xs[32][130];  // [k][token]
    __shared__ __align__(16) float ws[32][66];   // [k][expert]

    const int tid = threadIdx.x;
    if (blockIdx.x == 0 && blockIdx.y == 0 && tid < NEXP) g_cnt[tid] = 0;

    const int T0 = blockIdx.x * 128;
    const int d0 = blockIdx.y * DSPL_R;
    const int tr = tid >> 3;   // 0..15 -> 8 tokens each
    const int tc = tid & 7;    // 0..7  -> 8 experts each

    ull accP[4][4], accQ[4][4];
    #pragma unroll
    for (int m = 0; m < 4; m++)
        #pragma unroll
        for (int n = 0; n < 4; n++) { accP[m][n] = 0ull; accQ[m][n] = 0ull; }

    for (int dc = 0; dc < DSPL_R; dc += 32) {
        // x: 128 token rows x 32 d -> transposed store xs[d][t]
        #pragma unroll
        for (int ps = 0; ps < 8; ps++) {
            int r = (tid >> 3) + ps * 16;
            float4 v = *(const float4*)(x + (size_t)(T0 + r) * DIM + d0 + dc + tc * 4);
            xs[tc*4+0][r] = v.x; xs[tc*4+1][r] = v.y;
            xs[tc*4+2][r] = v.z; xs[tc*4+3][r] = v.w;
        }
        // W: 64 expert rows x 32 d -> transposed store ws[d][e]
        #pragma unroll
        for (int ps = 0; ps < 4; ps++) {
            int r = (tid >> 3) + ps * 16;
            float4 u = *(const float4*)(W + (size_t)r * DIM + d0 + dc + tc * 4);
            ws[tc*4+0][r] = u.x; ws[tc*4+1][r] = u.y;
            ws[tc*4+2][r] = u.z; ws[tc*4+3][r] = u.w;
        }
        __syncthreads();

        #pragma unroll
        for (int k = 0; k < 32; k++) {
            ull a[4], b[4], bs[4];
            #pragma unroll
            for (int m = 0; m < 4; m++) a[m] = *(const ull*)&xs[k][tr*8 + 2*m];
            #pragma unroll
            for (int n = 0; n < 4; n++) b[n] = *(const ull*)&ws[k][tc*8 + 2*n];
            #pragma unroll
            for (int n = 0; n < 4; n++) bs[n] = swap64(b[n]);
            #pragma unroll
            for (int m = 0; m < 4; m++)
                #pragma unroll
                for (int n = 0; n < 4; n++) {
                    accP[m][n] = fma2(a[m], b[n],  accP[m][n]);
                    accQ[m][n] = fma2(a[m], bs[n], accQ[m][n]);
                }
        }
        __syncthreads();
    }

    // epilogue: P=(a0b0,a1b1), Q=(a0b1,a1b0)
    float* dst = g_part + (size_t)blockIdx.y * TOKENS * NEXP;
    #pragma unroll
    for (int m = 0; m < 4; m++) {
        int row0 = T0 + tr*8 + 2*m;
        float r0[8], r1[8];
        #pragma unroll
        for (int n = 0; n < 4; n++) {
            float2 P = unpack2(accP[m][n]);
            float2 Q = unpack2(accQ[m][n]);
            r0[2*n] = P.x; r0[2*n+1] = Q.x;
            r1[2*n] = Q.y; r1[2*n+1] = P.y;
        }
        *(float4*)(dst + (size_t)row0 * NEXP + tc*8)     = make_float4(r0[0], r0[1], r0[2], r0[3]);
        *(float4*)(dst + (size_t)row0 * NEXP + tc*8 + 4) = make_float4(r0[4], r0[5], r0[6], r0[7]);
        *(float4*)(dst + (size_t)(row0+1) * NEXP + tc*8)     = make_float4(r1[0], r1[1], r1[2], r1[3]);
        *(float4*)(dst + (size_t)(row0+1) * NEXP + tc*8 + 4) = make_float4(r1[4], r1[5], r1[6], r1[7]);
    }
}

// ============================================================
// Kernel 2: combine partials, top-2, softmax, outputs, scatter.
// ============================================================
__global__ __launch_bounds__(256) void k_top2(float* __restrict__ out, int out_size) {
    int t = blockIdx.x * blockDim.x + threadIdx.x;

    float sc[64];
    {
        const float4* p = (const float4*)(g_part) + (size_t)t * 16;
        #pragma unroll
        for (int c = 0; c < 16; c++) {
            float4 v = p[c];
            sc[4*c+0] = v.x; sc[4*c+1] = v.y; sc[4*c+2] = v.z; sc[4*c+3] = v.w;
        }
    }
    #pragma unroll
    for (int s = 1; s < NSPL_R; s++) {
        const float4* p = (const float4*)(g_part + (size_t)s * TOKENS * NEXP) + (size_t)t * 16;
        #pragma unroll
        for (int c = 0; c < 16; c++) {
            float4 v = p[c];
            sc[4*c+0] += v.x; sc[4*c+1] += v.y; sc[4*c+2] += v.z; sc[4*c+3] += v.w;
        }
    }

    float m0 = -1e30f, m1 = -1e30f; int i0 = 0, i1 = 0;
    #pragma unroll
    for (int n = 0; n < NEXP; n++) {
        float v = sc[n];
        if (v > m0)      { m1 = m0; i1 = i0; m0 = v; i0 = n; }
        else if (v > m1) { m1 = v; i1 = n; }
    }
    float w0 = 1.0f / (1.0f + __expf(m1 - m0));
    float w1 = 1.0f - w0;

    g_w[t*2 + 0] = w0;
    g_w[t*2 + 1] = w1;
    if (out_size >= OFF_IDX + TOKENS*2) {
        out[OFF_IDX + t*2 + 0] = (float)i0;
        out[OFF_IDX + t*2 + 1] = (float)i1;
    }
    if (out_size >= OFF_W + TOKENS*2) {
        out[OFF_W + t*2 + 0] = w0;
        out[OFF_W + t*2 + 1] = w1;
    }
    int p = atomicAdd(&g_cnt[i0], 1);
    g_list[i0 * CAP + p] = t*2 + 0;
    p = atomicAdd(&g_cnt[i1], 1);
    g_list[i1 * CAP + p] = t*2 + 1;
}

// ============================================================
// Kernel 3: projection. Persistent blocks; per-block worklist scan
// (no separate tiles kernel). Tile: 128 picks x 64 rank, split-K x4.
// Same 8x8 f32x2 P/Q scheme. neurons are d-major already (no transpose).
// ============================================================
__global__ __launch_bounds__(128) void k_proj(
    const float* __restrict__ x, const float* __restrict__ neurons)
{
    __shared__ __align__(16) float xs[32][130];   // [d][pick]
    __shared__ __align__(16) float nsh[32][68];   // [d][r]
    __shared__ int psh[TILE_P];
    __shared__ int tsh[TILE_P];
    __shared__ int s_base[NEXP + 1];

    const int tid = threadIdx.x;
    const int tr = tid >> 3;   // 0..15 -> 8 picks each
    const int tc = tid & 7;    // 0..7  -> 8 r each

    if (tid == 0) {
        int sum = 0;
        for (int e = 0; e < NEXP; e++) {
            s_base[e] = sum;
            sum += (g_cnt[e] + TILE_P - 1) >> 7;
        }
        s_base[NEXP] = sum;
    }
    __syncthreads();
    const int nwork = s_base[NEXP] * NSPLIT;

    for (int w = blockIdx.x; w < nwork; w += gridDim.x) {
        const int it = w >> 2;
        const int sp = w & 3;
        int e = 0;
        while (s_base[e + 1] <= it) e++;
        const int off = (it - s_base[e]) * TILE_P;
        int cnt = g_cnt[e] - off;
        if (cnt > TILE_P) cnt = TILE_P;

        if (tid < TILE_P) {
            if (tid < cnt) {
                int p = g_list[e * CAP + off + tid];
                psh[tid] = p;
                tsh[tid] = p >> 1;
            } else {
                psh[tid] = -1;
                tsh[tid] = -1;
            }
        }
        __syncthreads();

        ull accP[4][4], accQ[4][4];
        #pragma unroll
        for (int m = 0; m < 4; m++)
            #pragma unroll
            for (int n = 0; n < 4; n++) { accP[m][n] = 0ull; accQ[m][n] = 0ull; }

        const float* nb = neurons + ((size_t)e * DIM + (size_t)sp * DSPL) * RANK;
        const int dbase = sp * DSPL;

        for (int dc = 0; dc < DSPL; dc += 32) {
            // gathered x: 128 pick rows x 32 d -> transposed xs[d][pick]
            #pragma unroll
            for (int ps = 0; ps < 8; ps++) {
                int r = (tid >> 3) + ps * 16;
                int tok = tsh[r];
                float4 v = make_float4(0.f, 0.f, 0.f, 0.f);
                if (tok >= 0)
                    v = *(const float4*)(x + (size_t)tok * DIM + dbase + dc + tc * 4);
                xs[tc*4+0][r] = v.x; xs[tc*4+1][r] = v.y;
                xs[tc*4+2][r] = v.z; xs[tc*4+3][r] = v.w;
            }
            // neurons: [32 d][64 r] direct (already k-major)
            #pragma unroll
            for (int ps = 0; ps < 4; ps++) {
                int d = (tid >> 4) + ps * 8;
                int c = tid & 15;
                *(float4*)&nsh[d][c*4] = *(const float4*)(nb + (size_t)(dc + d) * RANK + c*4);
            }
            __syncthreads();

            #pragma unroll
            for (int k = 0; k < 32; k++) {
                ull a[4], b[4], bs[4];
                #pragma unroll
                for (int m = 0; m < 4; m++) a[m] = *(const ull*)&xs[k][tr*8 + 2*m];
                #pragma unroll
                for (int n = 0; n < 4; n++) b[n] = *(const ull*)&nsh[k][tc*8 + 2*n];
                #pragma unroll
                for (int n = 0; n < 4; n++) bs[n] = swap64(b[n]);
                #pragma unroll
                for (int m = 0; m < 4; m++)
                    #pragma unroll
                    for (int n = 0; n < 4; n++) {
                        accP[m][n] = fma2(a[m], b[n],  accP[m][n]);
                        accQ[m][n] = fma2(a[m], bs[n], accQ[m][n]);
                    }
            }
            __syncthreads();
        }

        // epilogue: disjoint (split, pick) scratch rows
        float* sb = g_scratch + (size_t)sp * (TOKENS * 2) * RANK;
        #pragma unroll
        for (int m = 0; m < 4; m++) {
            int p0 = psh[tr*8 + 2*m];
            int p1 = psh[tr*8 + 2*m + 1];
            float r0[8], r1[8];
            #pragma unroll
            for (int n = 0; n < 4; n++) {
                float2 P = unpack2(accP[m][n]);
                float2 Q = unpack2(accQ[m][n]);
                r0[2*n] = P.x; r0[2*n+1] = Q.x;
                r1[2*n] = Q.y; r1[2*n+1] = P.y;
            }
            if (p0 >= 0) {
                *(float4*)(sb + (size_t)p0 * RANK + tc*8)     = make_float4(r0[0], r0[1], r0[2], r0[3]);
                *(float4*)(sb + (size_t)p0 * RANK + tc*8 + 4) = make_float4(r0[4], r0[5], r0[6], r0[7]);
            }
            if (p1 >= 0) {
                *(float4*)(sb + (size_t)p1 * RANK + tc*8)     = make_float4(r1[0], r1[1], r1[2], r1[3]);
                *(float4*)(sb + (size_t)p1 * RANK + tc*8 + 4) = make_float4(r1[4], r1[5], r1[6], r1[7]);
            }
        }
        __syncthreads();
    }
}

// ============================================================
// Kernel 4: deterministic reduce: out[t,r] = sum_k w_k * sum_s part
// ============================================================
__global__ __launch_bounds__(256) void k_reduce(float* __restrict__ out) {
    int i = blockIdx.x * blockDim.x + threadIdx.x;
    int t = i >> 4;
    int c = (i & 15) * 4;
    float4 acc = make_float4(0.f, 0.f, 0.f, 0.f);
    #pragma unroll
    for (int k = 0; k < 2; k++) {
        int p = t*2 + k;
        float w = g_w[p];
        #pragma unroll
        for (int s = 0; s < NSPLIT; s++) {
            float4 v = *(const float4*)&g_scratch[((size_t)s * (TOKENS*2) + p) * RANK + c];
            acc.x += w * v.x; acc.y += w * v.y; acc.z += w * v.z; acc.w += w * v.w;
        }
    }
    *(float4*)&out[(size_t)t * RANK + c] = acc;
}

// ============================================================
extern "C" void kernel_launch(void* const* d_in, const int* in_sizes, int n_in,
                              void* d_out, int out_size) {
    const float* x       = (const float*)d_in[0];
    const float* router  = (const float*)d_in[1];
    const float* neurons = (const float*)d_in[2];
    float* out = (float*)d_out;

    k_router<<<dim3(TOKENS / 128, NSPL_R), 128>>>(x, router);
    k_top2<<<TOKENS / 256, 256>>>(out, out_size);
    k_proj<<<444, 128>>>(x, neurons);
    k_reduce<<<TOKENS * RANK / 4 / 256, 256>>>(out);
}

// round 4
// speedup vs baseline: 1.0699x; 1.0699x over previous
#include <cuda_runtime.h>
#include <math.h>

// Problem: B=2, S=2048, D=1024, N_COMPRESS=64, RANK=64, TOP_K=2
#define TOKENS 4096
#define DIM    1024
#define NEXP   64
#define RANK   64
#define CAP    8192
#define NSPLIT 4          // proj D-splits (256 d each)
#define DSPL   256
#define TILE_P 128        // picks per proj tile

#define OFF_IDX (TOKENS * RANK)
#define OFF_W   (TOKENS * RANK + TOKENS*2)

typedef unsigned long long ull;

__device__ __forceinline__ ull fma2(ull a, ull b, ull c) {
    ull d; asm("fma.rn.f32x2 %0, %1, %2, %3;" : "=l"(d) : "l"(a), "l"(b), "l"(c)); return d;
}
__device__ __forceinline__ float2 unpack2(ull v) {
    float2 r; asm("mov.b64 {%0, %1}, %2;" : "=f"(r.x), "=f"(r.y) : "l"(v)); return r;
}

// ---- scratch (device globals) ----
__device__ int   g_cnt[NEXP];
__device__ int   g_list[NEXP * CAP];
__device__ float g_w[TOKENS * 2];
__device__ float g_part[2 * TOKENS * NEXP];             // router partials (2 D-splits)
__device__ float g_scratch[NSPLIT * TOKENS * 2 * RANK]; // proj partials

// ============================================================
// Kernel 1: router partial scores (R2-proven). grid (64, 2), 256 thr.
// 64 tokens x 64 experts per block over 512 d. 4x4 k-packed f32x2.
// g_cnt zeroing fused into block (0,0).
// ============================================================
__global__ __launch_bounds__(256) void k_router(
    const float* __restrict__ x, const float* __restrict__ W)
{
    __shared__ float xs[64][34];
    __shared__ float ws[64][34];

    const int tid = threadIdx.x;
    if (blockIdx.x == 0 && blockIdx.y == 0 && tid < NEXP) g_cnt[tid] = 0;

    const int ty  = tid >> 4;
    const int tx  = tid & 15;
    const int tok0 = blockIdx.x * 64;
    const int d0   = blockIdx.y * 512;

    ull acc[4][4];
    #pragma unroll
    for (int i = 0; i < 4; i++)
        #pragma unroll
        for (int j = 0; j < 4; j++) acc[i][j] = 0ull;

    for (int dc = 0; dc < 512; dc += 32) {
        #pragma unroll
        for (int r = 0; r < 2; r++) {
            int idx = tid + r * 256;
            int t = idx >> 3, c = idx & 7;
            float4 v = *(const float4*)(x + (size_t)(tok0 + t) * DIM + d0 + dc + 4 * c);
            xs[t][4*c+0] = v.x; xs[t][4*c+1] = v.y; xs[t][4*c+2] = v.z; xs[t][4*c+3] = v.w;
            float4 u = *(const float4*)(W + (size_t)t * DIM + d0 + dc + 4 * c);
            ws[t][4*c+0] = u.x; ws[t][4*c+1] = u.y; ws[t][4*c+2] = u.z; ws[t][4*c+3] = u.w;
        }
        __syncthreads();

        #pragma unroll
        for (int k = 0; k < 32; k += 2) {
            ull a[4], b[4];
            #pragma unroll
            for (int i = 0; i < 4; i++) a[i] = *(const ull*)&xs[ty + 16*i][k];
            #pragma unroll
            for (int j = 0; j < 4; j++) b[j] = *(const ull*)&ws[tx + 16*j][k];
            #pragma unroll
            for (int i = 0; i < 4; i++)
                #pragma unroll
                for (int j = 0; j < 4; j++)
                    acc[i][j] = fma2(a[i], b[j], acc[i][j]);
        }
        __syncthreads();
    }

    float* dst = g_part + (size_t)blockIdx.y * TOKENS * NEXP + (size_t)tok0 * NEXP;
    #pragma unroll
    for (int i = 0; i < 4; i++)
        #pragma unroll
        for (int j = 0; j < 4; j++) {
            float2 p = unpack2(acc[i][j]);
            dst[(ty + 16*i) * NEXP + tx + 16*j] = p.x + p.y;
        }
}

// ============================================================
// Kernel 2: combine 2 partials, top-2, softmax, outputs, scatter.
// ============================================================
__global__ __launch_bounds__(256) void k_top2(float* __restrict__ out, int out_size) {
    int t = blockIdx.x * blockDim.x + threadIdx.x;
    const float4* p0 = (const float4*)(g_part) + (size_t)t * 16;
    const float4* p1 = (const float4*)(g_part + (size_t)TOKENS * NEXP) + (size_t)t * 16;

    float m0 = -1e30f, m1 = -1e30f; int i0 = 0, i1 = 0;
    #pragma unroll
    for (int c = 0; c < 16; c++) {
        float4 a = p0[c], b = p1[c];
        float s[4] = { a.x + b.x, a.y + b.y, a.z + b.z, a.w + b.w };
        #pragma unroll
        for (int e = 0; e < 4; e++) {
            int n = 4*c + e;
            float v = s[e];
            if (v > m0)      { m1 = m0; i1 = i0; m0 = v; i0 = n; }
            else if (v > m1) { m1 = v; i1 = n; }
        }
    }
    float w0 = 1.0f / (1.0f + __expf(m1 - m0));
    float w1 = 1.0f - w0;

    g_w[t*2 + 0] = w0;
    g_w[t*2 + 1] = w1;
    if (out_size >= OFF_IDX + TOKENS*2) {
        out[OFF_IDX + t*2 + 0] = (float)i0;
        out[OFF_IDX + t*2 + 1] = (float)i1;
    }
    if (out_size >= OFF_W + TOKENS*2) {
        out[OFF_W + t*2 + 0] = w0;
        out[OFF_W + t*2 + 1] = w1;
    }
    int p = atomicAdd(&g_cnt[i0], 1);
    g_list[i0 * CAP + p] = t*2 + 0;
    p = atomicAdd(&g_cnt[i1], 1);
    g_list[i1 * CAP + p] = t*2 + 1;
}

// ============================================================
// Kernel 3: projection. 128 picks x 64 r per block, 256 threads,
// per-thread 8x4 k-packed f32x2. split-K x4, persistent blocks,
// in-kernel worklist (parallel smem scan). Partials to disjoint rows.
// ============================================================
__global__ __launch_bounds__(256, 2) void k_proj(
    const float* __restrict__ x, const float* __restrict__ neurons)
{
    __shared__ __align__(16) float xsh[TILE_P][36];  // [pick][k], stride 36 (float4 ok)
    __shared__ __align__(16) float nshT[RANK][34];   // [r][k], stride 34 (ull ok, b conflict-free)
    __shared__ int psh[TILE_P];
    __shared__ int tsh[TILE_P];
    __shared__ int s_nt[NEXP];
    __shared__ int s_base[NEXP + 1];

    const int tid = threadIdx.x;
    const int ty = tid >> 4;   // 0..15 -> 8 pick rows (ty + 16*i)
    const int tx = tid & 15;   // 0..15 -> 4 r cols (tx + 16*j)

    if (tid < NEXP) s_nt[tid] = (g_cnt[tid] + TILE_P - 1) >> 7;
    __syncthreads();
    if (tid == 0) {
        int sum = 0;
        #pragma unroll
        for (int e = 0; e < NEXP; e++) { s_base[e] = sum; sum += s_nt[e]; }
        s_base[NEXP] = sum;
    }
    __syncthreads();
    const int nwork = s_base[NEXP] * NSPLIT;

    for (int w = blockIdx.x; w < nwork; w += gridDim.x) {
        const int it = w >> 2;
        const int sp = w & 3;
        int e = 0;
        while (s_base[e + 1] <= it) e++;
        const int off = (it - s_base[e]) * TILE_P;
        int cnt = g_cnt[e] - off;
        if (cnt > TILE_P) cnt = TILE_P;

        if (tid < TILE_P) {
            if (tid < cnt) {
                int p = g_list[e * CAP + off + tid];
                psh[tid] = p;
                tsh[tid] = p >> 1;
            } else {
                psh[tid] = -1;
                tsh[tid] = -1;
            }
        }
        __syncthreads();

        ull acc[8][4];
        #pragma unroll
        for (int i = 0; i < 8; i++)
            #pragma unroll
            for (int j = 0; j < 4; j++) acc[i][j] = 0ull;

        const float* nb = neurons + ((size_t)e * DIM + (size_t)sp * DSPL) * RANK;
        const int dbase = sp * DSPL;

        for (int dc = 0; dc < DSPL; dc += 32) {
            // gathered x: 128 pick rows x 32 d (d-contig in gmem AND smem: direct copy)
            #pragma unroll
            for (int s = 0; s < 4; s++) {
                int idx = tid + 256 * s;        // 0..1023
                int pr = idx >> 3, c = idx & 7; // pick row, float4 col
                int tok = tsh[pr];
                float4 v = make_float4(0.f, 0.f, 0.f, 0.f);
                if (tok >= 0)
                    v = *(const float4*)(x + (size_t)tok * DIM + dbase + dc + 4 * c);
                *(float4*)&xsh[pr][4*c] = v;
            }
            // neurons [32 d][64 r] -> transposed nshT[r][d]
            #pragma unroll
            for (int s = 0; s < 2; s++) {
                int idx = tid + 256 * s;        // 0..511
                int d = idx >> 4, rc = idx & 15;
                float4 v = *(const float4*)(nb + (size_t)(dc + d) * RANK + rc * 4);
                nshT[4*rc+0][d] = v.x;
                nshT[4*rc+1][d] = v.y;
                nshT[4*rc+2][d] = v.z;
                nshT[4*rc+3][d] = v.w;
            }
            __syncthreads();

            #pragma unroll
            for (int k = 0; k < 32; k += 2) {
                ull a[8], b[4];
                #pragma unroll
                for (int j = 0; j < 4; j++) b[j] = *(const ull*)&nshT[tx + 16*j][k];
                #pragma unroll
                for (int i = 0; i < 8; i++) a[i] = *(const ull*)&xsh[ty + 16*i][k];
                #pragma unroll
                for (int i = 0; i < 8; i++)
                    #pragma unroll
                    for (int j = 0; j < 4; j++)
                        acc[i][j] = fma2(a[i], b[j], acc[i][j]);
            }
            __syncthreads();
        }

        // epilogue: disjoint (split, pick) scratch rows
        float* sb = g_scratch + (size_t)sp * (TOKENS * 2) * RANK;
        #pragma unroll
        for (int i = 0; i < 8; i++) {
            int p = psh[ty + 16*i];
            if (p >= 0) {
                #pragma unroll
                for (int j = 0; j < 4; j++) {
                    float2 v = unpack2(acc[i][j]);
                    sb[(size_t)p * RANK + tx + 16*j] = v.x + v.y;
                }
            }
        }
        __syncthreads();
    }
}

// ============================================================
// Kernel 4: deterministic reduce: out[t,r] = sum_k w_k * sum_s part
// ============================================================
__global__ __launch_bounds__(256) void k_reduce(float* __restrict__ out) {
    int i = blockIdx.x * blockDim.x + threadIdx.x;
    int t = i >> 4;
    int c = (i & 15) * 4;
    float4 acc = make_float4(0.f, 0.f, 0.f, 0.f);
    #pragma unroll
    for (int k = 0; k < 2; k++) {
        int p = t*2 + k;
        float w = g_w[p];
        #pragma unroll
        for (int s = 0; s < NSPLIT; s++) {
            float4 v = *(const float4*)&g_scratch[((size_t)s * (TOKENS*2) + p) * RANK + c];
            acc.x += w * v.x; acc.y += w * v.y; acc.z += w * v.z; acc.w += w * v.w;
        }
    }
    *(float4*)&out[(size_t)t * RANK + c] = acc;
}

// ============================================================
extern "C" void kernel_launch(void* const* d_in, const int* in_sizes, int n_in,
                              void* d_out, int out_size) {
    const float* x       = (const float*)d_in[0];
    const float* router  = (const float*)d_in[1];
    const float* neurons = (const float*)d_in[2];
    float* out = (float*)d_out;

    k_router<<<dim3(TOKENS/64, 2), 256>>>(x, router);
    k_top2<<<TOKENS/256, 256>>>(out, out_size);
    k_proj<<<296, 256>>>(x, neurons);
    k_reduce<<<TOKENS*RANK/4/256, 256>>>(out);
}